// round 10
// baseline (speedup 1.0000x reference)
#include <cuda_runtime.h>
#include <cstdint>
#include <math.h>

#define BB 4
#define CC 16
#define LLEN 1024
#define KK 5
#define TH 16
#define TW 64
#define NCHUNK 16                  // one ci per chunk
#define NBUF 4                     // 4-deep smem ring, lookahead 2
#define SROW 72                    // 64 + 4 halo, padded to 72 (16B-aligned rows)
#define SROWS (TH + 4)             // 20
#define CHUNK_ELEMS (SROWS * SROW)           // 1440 floats = 5.76 KB
#define NPAIRS (SROWS * 34)                  // 680 8B cp.async transfers per chunk

// Scratch for softmax probabilities. Only the causal half (j <= i) is ever
// written or read; the conv stager zero-fills everything else via cp.async
// src-size, so the above-diagonal region of this buffer is never touched.
__device__ float g_probs[(size_t)BB * CC * LLEN * LLEN];

// ---------------------------------------------------------------------------
// Packed f32x2 helpers (sm_103a FFMA2 — ptxas never emits this on its own)
// ---------------------------------------------------------------------------
__device__ __forceinline__ void ffma2(unsigned long long& acc,
                                      unsigned long long w,
                                      unsigned long long x) {
    asm("fma.rn.f32x2 %0, %1, %2, %0;" : "+l"(acc) : "l"(w), "l"(x));
}
__device__ __forceinline__ unsigned long long pack_dup(float v) {
    unsigned long long r;
    asm("mov.b64 %0, {%1, %1};" : "=l"(r) : "f"(v));
    return r;
}
__device__ __forceinline__ void unpack2(unsigned long long v, float& lo, float& hi) {
    asm("mov.b64 {%0, %1}, %2;" : "=f"(lo), "=f"(hi) : "l"(v));
}

// ---------------------------------------------------------------------------
// Pass 1: causal softmax over the last dim. One block per row (b,c,i).
// Reads AND writes only the causal half (j <= i): ~halves HBM traffic.
// ---------------------------------------------------------------------------
__global__ __launch_bounds__(256) void softmax_causal_kernel(const float* __restrict__ scores) {
    const int row = blockIdx.x;                 // (b*CC + c)*LLEN + i
    const int i   = row & (LLEN - 1);
    const float* src = scores + (size_t)row * LLEN;
    float* dst = g_probs + (size_t)row * LLEN;
    const int tid = threadIdx.x;

    float v[4];
    float mx = -INFINITY;
#pragma unroll
    for (int k = 0; k < 4; k++) {
        int j = tid + k * 256;
        v[k] = (j <= i) ? src[j] : -INFINITY;
        mx = fmaxf(mx, v[k]);
    }
#pragma unroll
    for (int o = 16; o; o >>= 1) mx = fmaxf(mx, __shfl_xor_sync(0xffffffffu, mx, o));

    __shared__ float smax[8];
    __shared__ float ssum[8];
    if ((tid & 31) == 0) smax[tid >> 5] = mx;
    __syncthreads();
    mx = smax[0];
#pragma unroll
    for (int w = 1; w < 8; w++) mx = fmaxf(mx, smax[w]);

    float e[4];
    float s = 0.f;
#pragma unroll
    for (int k = 0; k < 4; k++) {
        int j = tid + k * 256;
        e[k] = (j <= i) ? __expf(v[k] - mx) : 0.f;
        s += e[k];
    }
#pragma unroll
    for (int o = 16; o; o >>= 1) s += __shfl_xor_sync(0xffffffffu, s, o);
    if ((tid & 31) == 0) ssum[tid >> 5] = s;
    __syncthreads();
    s = ssum[0];
#pragma unroll
    for (int w = 1; w < 8; w++) s += ssum[w];

    const float inv = 1.0f / s;
#pragma unroll
    for (int k = 0; k < 4; k++) {
        int j = tid + k * 256;
        if (j <= i) dst[j] = e[k] * inv;      // causal half only
    }
}

// ---------------------------------------------------------------------------
// cp.async staging of ONE input channel's halo tile (8B transfers).
// src-size encodes both range AND causality: sz = clamp(gi-gj+1,0,2)*4,
// so above-diagonal / out-of-range bytes are hardware zero-filled and the
// softmax pass never has to write zeros to gmem.
// gj is always even (jt0 even, halo -2) -> every pair is row-aligned.
// ---------------------------------------------------------------------------
__device__ __forceinline__ void issue_chunk_loads(
        const float* __restrict__ probs_b,   // g_probs + batch plane base
        int i0, int jt0, int ci, float* sbuf, int tid)
{
    const unsigned int sbase = (unsigned int)__cvta_generic_to_shared(sbuf);
#pragma unroll
    for (int it = 0; it < (NPAIRS + 255) / 256; it++) {
        int e = tid + it * 256;
        if (e < NPAIRS) {
            int lr  = e / 34;
            int m   = e - lr * 34;
            int gi  = i0 - 2 + lr;
            int gj  = jt0 - 2 + 2 * m;
            bool okr = ((unsigned)gi < LLEN) && ((unsigned)gj < LLEN);
            int vis = gi - gj + 1;                       // causal elems in pair
            vis = vis < 0 ? 0 : (vis > 2 ? 2 : vis);
            int sz = okr ? vis * 4 : 0;
            const float* src = okr
                ? probs_b + ((size_t)ci * LLEN + gi) * LLEN + gj
                : probs_b;                               // valid addr, size 0
            unsigned int dst = sbase + (unsigned int)((lr * SROW + 2 * m) * 4);
            asm volatile("cp.async.ca.shared.global [%0], [%1], 8, %2;"
                         :: "r"(dst), "l"(src), "r"(sz));
        }
    }
}

// ---------------------------------------------------------------------------
// Pass 2: 5x5 dense-channel conv + bias + causal zero-mask.
// FFMA2 compute (co-pairs packed f32x2) + 4-deep cp.async ring (lookahead 2,
// ONE barrier per chunk). Tile: 16 rows x 64 cols x 16 co per block per batch.
// Thread = 4 co-pairs x 8 contiguous pixels (32 b64 accumulators).
// ---------------------------------------------------------------------------
__global__ __launch_bounds__(256, 2) void conv_causal_kernel(
        const float* __restrict__ weight,   // [co][ci][ki][kj], 16*16*5*5
        const float* __restrict__ bias,     // [16]
        float* __restrict__ out)            // [b][co][i][j]
{
    const int cjt = blockIdx.x;             // 0..15  column tile
    const int rit = blockIdx.y;             // 0..63  row tile
    const int b   = blockIdx.z;             // 0..3
    const int i0  = rit * TH;
    const int jt0 = cjt * TW;

    const int tid = threadIdx.x;
    const int cg  = tid >> 7;               // 0/1 -> co 0-7 / 8-15 (warp-uniform)
    const int pg  = tid & 127;
    const int r   = pg >> 3;                // 0..15 tile row
    const int j0  = (pg & 7) * 8;           // 0,8,..,56 tile col group
    const int co_base = cg * 8;

    unsigned long long acc[4][8];
#pragma unroll
    for (int c = 0; c < 4; c++)
#pragma unroll
        for (int p = 0; p < 8; p++) acc[c][p] = 0ull;

    const bool tile_causal = (jt0 <= i0 + TH - 1);

    __shared__ __align__(16) float s_w[CC * 25 * 16];          // 25.6 KB
    __shared__ __align__(16) float s_in[NBUF * CHUNK_ELEMS];   // 4 x 5.76 KB

    if (tile_causal) {
        const float* probs_b = g_probs + (size_t)b * CC * LLEN * LLEN;
        const float* pw_base = s_w + co_base;

        // Prologue: launch chunks 0 and 1 before anything else.
        issue_chunk_loads(probs_b, i0, jt0, 0, s_in, tid);
        asm volatile("cp.async.commit_group;" ::: "memory");
        issue_chunk_loads(probs_b, i0, jt0, 1, s_in + CHUNK_ELEMS, tid);
        asm volatile("cp.async.commit_group;" ::: "memory");

        // Stage weights while the first chunks are in flight:
        // layout [ci][tap][co], co innermost (broadcast LDS.128).
        for (int t = tid; t < CC * 25 * 16; t += 256) {
            int co  = t & 15;
            int tap = (t >> 4) % 25;
            int ci  = t / (16 * 25);
            s_w[t] = weight[(co * CC + ci) * 25 + tap];
        }

#pragma unroll 1
        for (int c = 0; c < NCHUNK; c++) {
            // Lookahead 2: stage chunk c+2 into buffer (c+2)&3. That buffer
            // was last read at compute(c-2), which every warp has finished
            // (all passed sync(c-1)). Empty commits keep wait_group uniform.
            if (c + 2 < NCHUNK)
                issue_chunk_loads(probs_b, i0, jt0, c + 2,
                                  s_in + ((c + 2) & (NBUF - 1)) * CHUNK_ELEMS, tid);
            asm volatile("cp.async.commit_group;" ::: "memory");
            asm volatile("cp.async.wait_group 2;" ::: "memory");
            __syncthreads();   // chunk c visible; also fences s_w on c==0

            const float* cur = s_in + (c & (NBUF - 1)) * CHUNK_ELEMS;
            const float* pin_base = cur + r * SROW + j0;
            const float* wci = pw_base + c * 400;
#pragma unroll 1
            for (int ki = 0; ki < 5; ki++) {
                const float* rp = pin_base + ki * SROW;    // 16B aligned
                float4 xa = *(const float4*)(rp);
                float4 xb = *(const float4*)(rp + 4);
                float4 xc = *(const float4*)(rp + 8);
                unsigned long long pv[12];
                pv[0]  = pack_dup(xa.x);  pv[1]  = pack_dup(xa.y);
                pv[2]  = pack_dup(xa.z);  pv[3]  = pack_dup(xa.w);
                pv[4]  = pack_dup(xb.x);  pv[5]  = pack_dup(xb.y);
                pv[6]  = pack_dup(xb.z);  pv[7]  = pack_dup(xb.w);
                pv[8]  = pack_dup(xc.x);  pv[9]  = pack_dup(xc.y);
                pv[10] = pack_dup(xc.z);  pv[11] = pack_dup(xc.w);

                const float* wk = wci + ki * 80;           // ki*5 taps * 16 co
#pragma unroll
                for (int kj = 0; kj < 5; kj++) {
                    const ulonglong2 wA = *(const ulonglong2*)(wk + kj * 16);
                    const ulonglong2 wB = *(const ulonglong2*)(wk + kj * 16 + 4);
#pragma unroll
                    for (int p = 0; p < 8; p++) {
                        const unsigned long long xv = pv[p + kj];
                        ffma2(acc[0][p], wA.x, xv);
                        ffma2(acc[1][p], wA.y, xv);
                        ffma2(acc[2][p], wB.x, xv);
                        ffma2(acc[3][p], wB.y, xv);
                    }
                }
            }
        }
    }

    // Store: bias + causal mask. Non-causal tiles fall through with acc==0.
    const int ig = i0 + r;
    const int jg = jt0 + j0;
#pragma unroll
    for (int c2 = 0; c2 < 4; c2++) {
        const int coA = co_base + 2 * c2;
        const float bA = bias[coA];
        const float bB = bias[coA + 1];
        float oA[8], oB[8];
#pragma unroll
        for (int p = 0; p < 8; p++) {
            float lo, hi;
            unpack2(acc[c2][p], lo, hi);
            const bool ok = (jg + p <= ig);
            oA[p] = ok ? (lo + bA) : 0.f;
            oB[p] = ok ? (hi + bB) : 0.f;
        }
        float* opA = out + ((size_t)((b * CC + coA) * LLEN) + ig) * LLEN + jg;
        float* opB = opA + (size_t)LLEN * LLEN;
        *(float4*)opA       = make_float4(oA[0], oA[1], oA[2], oA[3]);
        *(float4*)(opA + 4) = make_float4(oA[4], oA[5], oA[6], oA[7]);
        *(float4*)opB       = make_float4(oB[0], oB[1], oB[2], oB[3]);
        *(float4*)(opB + 4) = make_float4(oB[4], oB[5], oB[6], oB[7]);
    }
}

// ---------------------------------------------------------------------------
// Launch
// ---------------------------------------------------------------------------
extern "C" void kernel_launch(void* const* d_in, const int* in_sizes, int n_in,
                              void* d_out, int out_size) {
    const float* scores = (const float*)d_in[0];  // [4,16,1024,1024]
    const float* weight = (const float*)d_in[1];  // [16,16,5,5]
    const float* bias   = (const float*)d_in[2];  // [16]
    float* out = (float*)d_out;

    softmax_causal_kernel<<<BB * CC * LLEN, 256>>>(scores);

    dim3 grid(LLEN / TW, LLEN / TH, BB);
    conv_causal_kernel<<<grid, 256>>>(weight, bias, out);
}

// round 12
// speedup vs baseline: 1.1294x; 1.1294x over previous
#include <cuda_runtime.h>
#include <cstdint>
#include <math.h>

#define BB 4
#define CC 16
#define LLEN 1024
#define KK 5
#define TH 16
#define TW 64
#define CI_CHUNK 2
#define NCHUNK (CC / CI_CHUNK)     // 8
#define SROW 72                    // 64 + 4 halo, padded to 72 (16B-aligned rows)
#define SROWS (TH + 4)             // 20
#define CHUNK_ELEMS (CI_CHUNK * SROWS * SROW)   // 2880 floats = 11.5 KB
#define NPAIRS (CI_CHUNK * SROWS * 34)          // 8B cp.async transfers per chunk

// Scratch for softmax probabilities. Only the causal half (j <= i) is ever
// written or read; the conv stager zero-fills everything else via cp.async
// src-size, so the above-diagonal region is never touched in gmem.
__device__ float g_probs[(size_t)BB * CC * LLEN * LLEN];

// ---------------------------------------------------------------------------
// Packed f32x2 helpers (sm_103a FFMA2 — ptxas never emits this on its own)
// ---------------------------------------------------------------------------
__device__ __forceinline__ void ffma2(unsigned long long& acc,
                                      unsigned long long w,
                                      unsigned long long x) {
    asm("fma.rn.f32x2 %0, %1, %2, %0;" : "+l"(acc) : "l"(w), "l"(x));
}
__device__ __forceinline__ unsigned long long pack_dup(float v) {
    unsigned long long r;
    asm("mov.b64 %0, {%1, %1};" : "=l"(r) : "f"(v));
    return r;
}
__device__ __forceinline__ void unpack2(unsigned long long v, float& lo, float& hi) {
    asm("mov.b64 {%0, %1}, %2;" : "=f"(lo), "=f"(hi) : "l"(v));
}

// ---------------------------------------------------------------------------
// Pass 1: causal softmax, ONE WARP PER ROW. 32 float4 registers hold the
// whole 1024-row; reductions are pure warp shuffles (no smem / syncthreads).
// 8 warps/block x up-to-8 blocks/SM = 64 rows in flight per SM (vs 8 before)
// -> latency-bound time drops toward the ~32us bandwidth floor.
// Loads AND stores are predicated to the causal half (j <= i).
// ---------------------------------------------------------------------------
__global__ __launch_bounds__(256) void softmax_causal_kernel(const float* __restrict__ scores) {
    const int row  = blockIdx.x * 8 + (threadIdx.x >> 5);   // (b*CC + c)*LLEN + i
    const int lane = threadIdx.x & 31;
    const int i    = row & (LLEN - 1);
    const float* src = scores + (size_t)row * LLEN;
    float* dst = g_probs + (size_t)row * LLEN;

    float4 v[8];
    float mx = -INFINITY;
#pragma unroll
    for (int k = 0; k < 8; k++) {
        const int j4 = (k * 32 + lane) * 4;
        float4 t = make_float4(-INFINITY, -INFINITY, -INFINITY, -INFINITY);
        if (j4 <= i) {                       // skip fully non-causal quads
            t = *(const float4*)(src + j4);
            if (j4 + 1 > i) t.y = -INFINITY;
            if (j4 + 2 > i) t.z = -INFINITY;
            if (j4 + 3 > i) t.w = -INFINITY;
        }
        v[k] = t;
        mx = fmaxf(mx, fmaxf(fmaxf(t.x, t.y), fmaxf(t.z, t.w)));
    }
#pragma unroll
    for (int o = 16; o; o >>= 1) mx = fmaxf(mx, __shfl_xor_sync(0xffffffffu, mx, o));

    float s = 0.f;
#pragma unroll
    for (int k = 0; k < 8; k++) {
        float4 t = v[k];
        t.x = (t.x == -INFINITY) ? 0.f : __expf(t.x - mx);
        t.y = (t.y == -INFINITY) ? 0.f : __expf(t.y - mx);
        t.z = (t.z == -INFINITY) ? 0.f : __expf(t.z - mx);
        t.w = (t.w == -INFINITY) ? 0.f : __expf(t.w - mx);
        v[k] = t;
        s += (t.x + t.y) + (t.z + t.w);
    }
#pragma unroll
    for (int o = 16; o; o >>= 1) s += __shfl_xor_sync(0xffffffffu, s, o);
    const float inv = 1.0f / s;

#pragma unroll
    for (int k = 0; k < 8; k++) {
        const int j4 = (k * 32 + lane) * 4;
        if (j4 + 3 <= i) {
            float4 t = v[k];
            *(float4*)(dst + j4) = make_float4(t.x * inv, t.y * inv, t.z * inv, t.w * inv);
        } else if (j4 <= i) {                // diagonal-straddling quad
            float e[4] = {v[k].x, v[k].y, v[k].z, v[k].w};
#pragma unroll
            for (int q = 0; q < 4; q++)
                if (j4 + q <= i) dst[j4 + q] = e[q] * inv;
        }
    }
}

// ---------------------------------------------------------------------------
// cp.async staging of one CI_CHUNK input halo tile (8B transfers).
// src-size encodes range AND causality: sz = clamp(gi-gj+1,0,2)*4, so
// above-diagonal / out-of-range bytes are hardware zero-filled.
// gj is always even (jt0 even, halo -2) -> every pair is row-aligned.
// ---------------------------------------------------------------------------
__device__ __forceinline__ void issue_chunk_loads(
        const float* __restrict__ probs_b,   // g_probs + batch plane base
        int i0, int jt0, int cc, float* sbuf, int tid)
{
    const unsigned int sbase = (unsigned int)__cvta_generic_to_shared(sbuf);
#pragma unroll
    for (int it = 0; it < (NPAIRS + 255) / 256; it++) {
        int e = tid + it * 256;
        if (e < NPAIRS) {
            int ci  = e / (SROWS * 34);
            int rem = e - ci * (SROWS * 34);
            int lr  = rem / 34;
            int m   = rem - lr * 34;
            int gi  = i0 - 2 + lr;
            int gj  = jt0 - 2 + 2 * m;
            bool okr = ((unsigned)gi < LLEN) && ((unsigned)gj < LLEN);
            int vis = gi - gj + 1;                       // causal elems in pair
            vis = vis < 0 ? 0 : (vis > 2 ? 2 : vis);
            int sz = okr ? vis * 4 : 0;
            const float* src = okr
                ? probs_b + ((size_t)(cc + ci) * LLEN + gi) * LLEN + gj
                : probs_b;                               // valid addr, size 0
            unsigned int dst = sbase + (unsigned int)(((ci * SROWS + lr) * SROW + 2 * m) * 4);
            asm volatile("cp.async.ca.shared.global [%0], [%1], 8, %2;"
                         :: "r"(dst), "l"(src), "r"(sz));
        }
    }
}

// ---------------------------------------------------------------------------
// Pass 2: 5x5 dense-channel conv + bias + causal zero-mask.
// R8 structure (best measured): CI_CHUNK=2, double buffer, lookahead 1.
// FFMA2 compute: thread = 4 co-pairs (packed f32x2) x 8 contiguous pixels.
// ---------------------------------------------------------------------------
__global__ __launch_bounds__(256, 2) void conv_causal_kernel(
        const float* __restrict__ weight,   // [co][ci][ki][kj], 16*16*5*5
        const float* __restrict__ bias,     // [16]
        float* __restrict__ out)            // [b][co][i][j]
{
    const int cjt = blockIdx.x;             // 0..15  column tile
    const int rit = blockIdx.y;             // 0..63  row tile
    const int b   = blockIdx.z;             // 0..3
    const int i0  = rit * TH;
    const int jt0 = cjt * TW;

    const int tid = threadIdx.x;
    const int cg  = tid >> 7;               // 0/1 -> co 0-7 / 8-15 (warp-uniform)
    const int pg  = tid & 127;
    const int r   = pg >> 3;                // 0..15 tile row
    const int j0  = (pg & 7) * 8;           // 0,8,..,56 tile col group
    const int co_base = cg * 8;

    unsigned long long acc[4][8];
#pragma unroll
    for (int c = 0; c < 4; c++)
#pragma unroll
        for (int p = 0; p < 8; p++) acc[c][p] = 0ull;

    const bool tile_causal = (jt0 <= i0 + TH - 1);

    __shared__ __align__(16) float s_w[CC * 25 * 16];          // 25.6 KB
    __shared__ __align__(16) float s_in[2 * CHUNK_ELEMS];      // 2 x 11.5 KB

    if (tile_causal) {
        const float* probs_b = g_probs + (size_t)b * CC * LLEN * LLEN;
        const float* pw_base = s_w + co_base;

        // Prologue: stage chunk 0 first, then weights overlap its flight.
        issue_chunk_loads(probs_b, i0, jt0, 0, s_in, tid);
        asm volatile("cp.async.commit_group;" ::: "memory");

        // Stage weights: [ci][tap][co], co innermost (broadcast LDS.128).
        for (int t = tid; t < CC * 25 * 16; t += 256) {
            int co  = t & 15;
            int tap = (t >> 4) % 25;
            int ci  = t / (16 * 25);
            s_w[t] = weight[(co * CC + ci) * 25 + tap];
        }

#pragma unroll 1
        for (int c = 0; c < NCHUNK; c++) {
            float* cur = s_in + (c & 1) * CHUNK_ELEMS;
            if (c < NCHUNK - 1) {
                issue_chunk_loads(probs_b, i0, jt0, (c + 1) * CI_CHUNK,
                                  s_in + ((c + 1) & 1) * CHUNK_ELEMS, tid);
                asm volatile("cp.async.commit_group;" ::: "memory");
                asm volatile("cp.async.wait_group 1;" ::: "memory");
            } else {
                asm volatile("cp.async.wait_group 0;" ::: "memory");
            }
            __syncthreads();   // chunk c visible to all (also fences s_w on c==0)

            const float* pin_base = cur + r * SROW + j0;
#pragma unroll 1
            for (int ci = 0; ci < CI_CHUNK; ci++) {
                const float* wci = pw_base + (c * CI_CHUNK + ci) * 400;
                const float* ici = pin_base + ci * (SROWS * SROW);
#pragma unroll 1
                for (int ki = 0; ki < 5; ki++) {
                    const float* rp = ici + ki * SROW;     // 16B aligned
                    float4 xa = *(const float4*)(rp);
                    float4 xb = *(const float4*)(rp + 4);
                    float4 xc = *(const float4*)(rp + 8);
                    unsigned long long pv[12];
                    pv[0]  = pack_dup(xa.x);  pv[1]  = pack_dup(xa.y);
                    pv[2]  = pack_dup(xa.z);  pv[3]  = pack_dup(xa.w);
                    pv[4]  = pack_dup(xb.x);  pv[5]  = pack_dup(xb.y);
                    pv[6]  = pack_dup(xb.z);  pv[7]  = pack_dup(xb.w);
                    pv[8]  = pack_dup(xc.x);  pv[9]  = pack_dup(xc.y);
                    pv[10] = pack_dup(xc.z);  pv[11] = pack_dup(xc.w);

                    const float* wk = wci + ki * 80;       // ki*5 taps * 16 co
#pragma unroll
                    for (int kj = 0; kj < 5; kj++) {
                        const ulonglong2 wA = *(const ulonglong2*)(wk + kj * 16);
                        const ulonglong2 wB = *(const ulonglong2*)(wk + kj * 16 + 4);
#pragma unroll
                        for (int p = 0; p < 8; p++) {
                            const unsigned long long xv = pv[p + kj];
                            ffma2(acc[0][p], wA.x, xv);
                            ffma2(acc[1][p], wA.y, xv);
                            ffma2(acc[2][p], wB.x, xv);
                            ffma2(acc[3][p], wB.y, xv);
                        }
                    }
                }
            }
            __syncthreads();   // all reads of cur done before iter c+1 overwrites it
        }
    }

    // Store: bias + causal mask. Non-causal tiles fall through with acc==0.
    const int ig = i0 + r;
    const int jg = jt0 + j0;
#pragma unroll
    for (int c2 = 0; c2 < 4; c2++) {
        const int coA = co_base + 2 * c2;
        const float bA = bias[coA];
        const float bB = bias[coA + 1];
        float oA[8], oB[8];
#pragma unroll
        for (int p = 0; p < 8; p++) {
            float lo, hi;
            unpack2(acc[c2][p], lo, hi);
            const bool ok = (jg + p <= ig);
            oA[p] = ok ? (lo + bA) : 0.f;
            oB[p] = ok ? (hi + bB) : 0.f;
        }
        float* opA = out + ((size_t)((b * CC + coA) * LLEN) + ig) * LLEN + jg;
        float* opB = opA + (size_t)LLEN * LLEN;
        *(float4*)opA       = make_float4(oA[0], oA[1], oA[2], oA[3]);
        *(float4*)(opA + 4) = make_float4(oA[4], oA[5], oA[6], oA[7]);
        *(float4*)opB       = make_float4(oB[0], oB[1], oB[2], oB[3]);
        *(float4*)(opB + 4) = make_float4(oB[4], oB[5], oB[6], oB[7]);
    }
}

// ---------------------------------------------------------------------------
// Launch
// ---------------------------------------------------------------------------
extern "C" void kernel_launch(void* const* d_in, const int* in_sizes, int n_in,
                              void* d_out, int out_size) {
    const float* scores = (const float*)d_in[0];  // [4,16,1024,1024]
    const float* weight = (const float*)d_in[1];  // [16,16,5,5]
    const float* bias   = (const float*)d_in[2];  // [16]
    float* out = (float*)d_out;

    softmax_causal_kernel<<<BB * CC * LLEN / 8, 256>>>(scores);

    dim3 grid(LLEN / TW, LLEN / TH, BB);
    conv_causal_kernel<<<grid, 256>>>(weight, bias, out);
}

// round 14
// speedup vs baseline: 1.1656x; 1.0321x over previous
#include <cuda_runtime.h>
#include <cstdint>
#include <math.h>

#define BB 4
#define CC 16
#define LLEN 1024
#define KK 5
#define TH 16
#define TW 64
#define CI_CHUNK 2
#define NCHUNK (CC / CI_CHUNK)     // 8
#define NBUF 3                     // 3-deep smem ring, single barrier per chunk
#define SROW 72                    // 64 + 4 halo, padded to 72 (16B-aligned rows)
#define SROWS (TH + 4)             // 20
#define CHUNK_ELEMS (CI_CHUNK * SROWS * SROW)   // 2880 floats = 11.5 KB
#define NPAIRS (CI_CHUNK * SROWS * 34)          // 1360 8B in-transfers per chunk
#define WCHUNK (CI_CHUNK * 25 * 16)             // 800 floats = 3.2 KB per chunk
#define WPAIRS (WCHUNK / 2)                     // 400 8B w-transfers per chunk

// Scratch: softmax probabilities (only causal half ever written/read) and
// transposed weights [ci][tap][co] for contiguous co-pair cp.async staging.
__device__ float g_probs[(size_t)BB * CC * LLEN * LLEN];
__device__ float g_wt[CC * 25 * 16];

// ---------------------------------------------------------------------------
// Packed f32x2 helpers (sm_103a FFMA2 — ptxas never emits this on its own)
// ---------------------------------------------------------------------------
__device__ __forceinline__ void ffma2(unsigned long long& acc,
                                      unsigned long long w,
                                      unsigned long long x) {
    asm("fma.rn.f32x2 %0, %1, %2, %0;" : "+l"(acc) : "l"(w), "l"(x));
}
__device__ __forceinline__ unsigned long long pack_dup(float v) {
    unsigned long long r;
    asm("mov.b64 %0, {%1, %1};" : "=l"(r) : "f"(v));
    return r;
}
__device__ __forceinline__ void unpack2(unsigned long long v, float& lo, float& hi) {
    asm("mov.b64 {%0, %1}, %2;" : "=f"(lo), "=f"(hi) : "l"(v));
}

// ---------------------------------------------------------------------------
// Pass 0: one-time weight transpose [co][ci][tap] -> [ci][tap][co] so the
// conv stager can fetch co-contiguous 8B pairs with cp.async.
// ---------------------------------------------------------------------------
__global__ void weight_transform_kernel(const float* __restrict__ weight) {
    for (int t = threadIdx.x; t < CC * 25 * 16; t += blockDim.x) {
        int co  = t & 15;
        int tap = (t >> 4) % 25;
        int ci  = t / (16 * 25);
        g_wt[t] = weight[(co * CC + ci) * 25 + tap];
    }
}

// ---------------------------------------------------------------------------
// Pass 1: causal softmax, ONE WARP PER ROW (pure shuffle reductions).
// Loads AND stores predicated to the causal half (j <= i).
// ---------------------------------------------------------------------------
__global__ __launch_bounds__(256) void softmax_causal_kernel(const float* __restrict__ scores) {
    const int row  = blockIdx.x * 8 + (threadIdx.x >> 5);   // (b*CC + c)*LLEN + i
    const int lane = threadIdx.x & 31;
    const int i    = row & (LLEN - 1);
    const float* src = scores + (size_t)row * LLEN;
    float* dst = g_probs + (size_t)row * LLEN;

    float4 v[8];
    float mx = -INFINITY;
#pragma unroll
    for (int k = 0; k < 8; k++) {
        const int j4 = (k * 32 + lane) * 4;
        float4 t = make_float4(-INFINITY, -INFINITY, -INFINITY, -INFINITY);
        if (j4 <= i) {
            t = *(const float4*)(src + j4);
            if (j4 + 1 > i) t.y = -INFINITY;
            if (j4 + 2 > i) t.z = -INFINITY;
            if (j4 + 3 > i) t.w = -INFINITY;
        }
        v[k] = t;
        mx = fmaxf(mx, fmaxf(fmaxf(t.x, t.y), fmaxf(t.z, t.w)));
    }
#pragma unroll
    for (int o = 16; o; o >>= 1) mx = fmaxf(mx, __shfl_xor_sync(0xffffffffu, mx, o));

    float s = 0.f;
#pragma unroll
    for (int k = 0; k < 8; k++) {
        float4 t = v[k];
        t.x = (t.x == -INFINITY) ? 0.f : __expf(t.x - mx);
        t.y = (t.y == -INFINITY) ? 0.f : __expf(t.y - mx);
        t.z = (t.z == -INFINITY) ? 0.f : __expf(t.z - mx);
        t.w = (t.w == -INFINITY) ? 0.f : __expf(t.w - mx);
        v[k] = t;
        s += (t.x + t.y) + (t.z + t.w);
    }
#pragma unroll
    for (int o = 16; o; o >>= 1) s += __shfl_xor_sync(0xffffffffu, s, o);
    const float inv = 1.0f / s;

#pragma unroll
    for (int k = 0; k < 8; k++) {
        const int j4 = (k * 32 + lane) * 4;
        if (j4 + 3 <= i) {
            float4 t = v[k];
            *(float4*)(dst + j4) = make_float4(t.x * inv, t.y * inv, t.z * inv, t.w * inv);
        } else if (j4 <= i) {
            float e[4] = {v[k].x, v[k].y, v[k].z, v[k].w};
#pragma unroll
            for (int q = 0; q < 4; q++)
                if (j4 + q <= i) dst[j4 + q] = e[q] * inv;
        }
    }
}

// ---------------------------------------------------------------------------
// cp.async staging of one chunk: CI_CHUNK input halo planes + that chunk's
// weights. Input src-size encodes range AND causality (hardware zero-fill):
// sz = clamp(gi-gj+1,0,2)*4. gj always even -> pairs never split rows.
// ---------------------------------------------------------------------------
__device__ __forceinline__ void issue_chunk_loads(
        const float* __restrict__ probs_b,   // g_probs + batch plane base
        int i0, int jt0, int cc, float* sbuf, float* wbuf, int tid)
{
    const unsigned int sbase = (unsigned int)__cvta_generic_to_shared(sbuf);
#pragma unroll
    for (int it = 0; it < (NPAIRS + 255) / 256; it++) {
        int e = tid + it * 256;
        if (e < NPAIRS) {
            int ci  = e / (SROWS * 34);
            int rem = e - ci * (SROWS * 34);
            int lr  = rem / 34;
            int m   = rem - lr * 34;
            int gi  = i0 - 2 + lr;
            int gj  = jt0 - 2 + 2 * m;
            bool okr = ((unsigned)gi < LLEN) && ((unsigned)gj < LLEN);
            int vis = gi - gj + 1;                       // causal elems in pair
            vis = vis < 0 ? 0 : (vis > 2 ? 2 : vis);
            int sz = okr ? vis * 4 : 0;
            const float* src = okr
                ? probs_b + ((size_t)(cc + ci) * LLEN + gi) * LLEN + gj
                : probs_b;                               // valid addr, size 0
            unsigned int dst = sbase + (unsigned int)(((ci * SROWS + lr) * SROW + 2 * m) * 4);
            asm volatile("cp.async.ca.shared.global [%0], [%1], 8, %2;"
                         :: "r"(dst), "l"(src), "r"(sz));
        }
    }
    // Weights for this chunk: contiguous [2ci][25tap][16co] block, 8B pairs.
    // NOTE: WPAIRS(400) > blockDim(256) -> must LOOP, not predicate once.
    const unsigned int wbase = (unsigned int)__cvta_generic_to_shared(wbuf);
#pragma unroll
    for (int it = 0; it < (WPAIRS + 255) / 256; it++) {
        int e = tid + it * 256;
        if (e < WPAIRS) {
            const float* wsrc = g_wt + cc * (25 * 16) + 2 * e;
            unsigned int wdst = wbase + (unsigned int)(8 * e);
            asm volatile("cp.async.ca.shared.global [%0], [%1], 8, 8;"
                         :: "r"(wdst), "l"(wsrc));
        }
    }
}

// ---------------------------------------------------------------------------
// Pass 2: 5x5 dense-channel conv + bias + causal zero-mask.
// FFMA2 compute (4 co-pairs x 8 pixels per thread), 3-buffer cp.async ring,
// ONE barrier per chunk, weights streamed per-chunk through the same ring.
// ---------------------------------------------------------------------------
__global__ __launch_bounds__(256, 2) void conv_causal_kernel(
        const float* __restrict__ bias,     // [16]
        float* __restrict__ out)            // [b][co][i][j]
{
    const int cjt = blockIdx.x;             // 0..15  column tile
    const int rit = blockIdx.y;             // 0..63  row tile
    const int b   = blockIdx.z;             // 0..3
    const int i0  = rit * TH;
    const int jt0 = cjt * TW;

    const int tid = threadIdx.x;
    const int cg  = tid >> 7;               // 0/1 -> co 0-7 / 8-15 (warp-uniform)
    const int pg  = tid & 127;
    const int r   = pg >> 3;                // 0..15 tile row
    const int j0  = (pg & 7) * 8;           // 0,8,..,56 tile col group
    const int co_base = cg * 8;

    unsigned long long acc[4][8];
#pragma unroll
    for (int c = 0; c < 4; c++)
#pragma unroll
        for (int p = 0; p < 8; p++) acc[c][p] = 0ull;

    const bool tile_causal = (jt0 <= i0 + TH - 1);

    __shared__ __align__(16) float s_in[NBUF * CHUNK_ELEMS];   // 3 x 11.52 KB
    __shared__ __align__(16) float s_w[NBUF * WCHUNK];         // 3 x 3.2 KB

    if (tile_causal) {
        const float* probs_b = g_probs + (size_t)b * CC * LLEN * LLEN;

        // Prologue: stage chunk 0 (inputs + weights).
        issue_chunk_loads(probs_b, i0, jt0, 0, s_in, s_w, tid);
        asm volatile("cp.async.commit_group;" ::: "memory");

#pragma unroll 1
        for (int c = 0; c < NCHUNK; c++) {
            // Stage chunk c+1 into ring slot (c+1)%3. That slot was last read
            // during compute(c-2); every warp has passed sync(c-1), so it is
            // drained. Unconditional commit keeps wait_group counts exact.
            if (c + 1 < NCHUNK)
                issue_chunk_loads(probs_b, i0, jt0, (c + 1) * CI_CHUNK,
                                  s_in + ((c + 1) % NBUF) * CHUNK_ELEMS,
                                  s_w  + ((c + 1) % NBUF) * WCHUNK, tid);
            asm volatile("cp.async.commit_group;" ::: "memory");
            asm volatile("cp.async.wait_group 1;" ::: "memory");
            __syncthreads();   // single barrier per chunk: chunk c visible

            const float* cur = s_in + (c % NBUF) * CHUNK_ELEMS;
            const float* pin_base = cur + r * SROW + j0;
            const float* pw_base  = s_w + (c % NBUF) * WCHUNK + co_base;
#pragma unroll 1
            for (int ci = 0; ci < CI_CHUNK; ci++) {
                const float* wci = pw_base + ci * 400;
                const float* ici = pin_base + ci * (SROWS * SROW);
#pragma unroll 1
                for (int ki = 0; ki < 5; ki++) {
                    const float* rp = ici + ki * SROW;     // 16B aligned
                    float4 xa = *(const float4*)(rp);
                    float4 xb = *(const float4*)(rp + 4);
                    float4 xc = *(const float4*)(rp + 8);
                    unsigned long long pv[12];
                    pv[0]  = pack_dup(xa.x);  pv[1]  = pack_dup(xa.y);
                    pv[2]  = pack_dup(xa.z);  pv[3]  = pack_dup(xa.w);
                    pv[4]  = pack_dup(xb.x);  pv[5]  = pack_dup(xb.y);
                    pv[6]  = pack_dup(xb.z);  pv[7]  = pack_dup(xb.w);
                    pv[8]  = pack_dup(xc.x);  pv[9]  = pack_dup(xc.y);
                    pv[10] = pack_dup(xc.z);  pv[11] = pack_dup(xc.w);

                    const float* wk = wci + ki * 80;       // ki*5 taps * 16 co
#pragma unroll
                    for (int kj = 0; kj < 5; kj++) {
                        const ulonglong2 wA = *(const ulonglong2*)(wk + kj * 16);
                        const ulonglong2 wB = *(const ulonglong2*)(wk + kj * 16 + 4);
#pragma unroll
                        for (int p = 0; p < 8; p++) {
                            const unsigned long long xv = pv[p + kj];
                            ffma2(acc[0][p], wA.x, xv);
                            ffma2(acc[1][p], wA.y, xv);
                            ffma2(acc[2][p], wB.x, xv);
                            ffma2(acc[3][p], wB.y, xv);
                        }
                    }
                }
            }
        }
    }

    // Store: bias + causal mask. Non-causal tiles fall through with acc==0.
    const int ig = i0 + r;
    const int jg = jt0 + j0;
#pragma unroll
    for (int c2 = 0; c2 < 4; c2++) {
        const int coA = co_base + 2 * c2;
        const float bA = bias[coA];
        const float bB = bias[coA + 1];
        float oA[8], oB[8];
#pragma unroll
        for (int p = 0; p < 8; p++) {
            float lo, hi;
            unpack2(acc[c2][p], lo, hi);
            const bool ok = (jg + p <= ig);
            oA[p] = ok ? (lo + bA) : 0.f;
            oB[p] = ok ? (hi + bB) : 0.f;
        }
        float* opA = out + ((size_t)((b * CC + coA) * LLEN) + ig) * LLEN + jg;
        float* opB = opA + (size_t)LLEN * LLEN;
        *(float4*)opA       = make_float4(oA[0], oA[1], oA[2], oA[3]);
        *(float4*)(opA + 4) = make_float4(oA[4], oA[5], oA[6], oA[7]);
        *(float4*)opB       = make_float4(oB[0], oB[1], oB[2], oB[3]);
        *(float4*)(opB + 4) = make_float4(oB[4], oB[5], oB[6], oB[7]);
    }
}

// ---------------------------------------------------------------------------
// Launch
// ---------------------------------------------------------------------------
extern "C" void kernel_launch(void* const* d_in, const int* in_sizes, int n_in,
                              void* d_out, int out_size) {
    const float* scores = (const float*)d_in[0];  // [4,16,1024,1024]
    const float* weight = (const float*)d_in[1];  // [16,16,5,5]
    const float* bias   = (const float*)d_in[2];  // [16]
    float* out = (float*)d_out;

    weight_transform_kernel<<<1, 256>>>(weight);
    softmax_causal_kernel<<<BB * CC * LLEN / 8, 256>>>(scores);

    dim3 grid(LLEN / TW, LLEN / TH, BB);
    conv_causal_kernel<<<grid, 256>>>(bias, out);
}

// round 15
// speedup vs baseline: 1.1951x; 1.0253x over previous
#include <cuda_runtime.h>
#include <cstdint>
#include <math.h>

#define BB 4
#define CC 16
#define LLEN 1024
#define KK 5
#define TH 16
#define TW 64
#define CI_CHUNK 2
#define NCHUNK (CC / CI_CHUNK)     // 8
#define NBUF 3                     // 3-deep smem ring, single barrier per chunk
#define SROW 72                    // 64 + 4 halo, padded to 72 (16B-aligned rows)
#define SROWS (TH + 4)             // 20
#define CHUNK_ELEMS (CI_CHUNK * SROWS * SROW)   // 2880 floats = 11.5 KB
#define NPAIRS (CI_CHUNK * SROWS * 34)          // 1360 8B in-transfers per chunk
#define WCHUNK (CI_CHUNK * 25 * 16)             // 800 floats = 3.2 KB per chunk
#define WPAIRS (WCHUNK / 2)                     // 400 8B w-transfers per chunk

// Scratch: softmax probabilities (only causal half ever written/read) and
// transposed weights [ci][tap][co] for contiguous co-pair cp.async staging.
__device__ float g_probs[(size_t)BB * CC * LLEN * LLEN];
__device__ float g_wt[CC * 25 * 16];

// ---------------------------------------------------------------------------
// Packed f32x2 helpers (sm_103a FFMA2 — ptxas never emits this on its own)
// ---------------------------------------------------------------------------
__device__ __forceinline__ void ffma2(unsigned long long& acc,
                                      unsigned long long w,
                                      unsigned long long x) {
    asm("fma.rn.f32x2 %0, %1, %2, %0;" : "+l"(acc) : "l"(w), "l"(x));
}
__device__ __forceinline__ unsigned long long pack_dup(float v) {
    unsigned long long r;
    asm("mov.b64 %0, {%1, %1};" : "=l"(r) : "f"(v));
    return r;
}
__device__ __forceinline__ void unpack2(unsigned long long v, float& lo, float& hi) {
    asm("mov.b64 {%0, %1}, %2;" : "=f"(lo), "=f"(hi) : "l"(v));
}

// ---------------------------------------------------------------------------
// Pass 1: causal softmax, ONE WARP PER ROW (pure shuffle reductions),
// plus one extra block that performs the weight transpose
// [co][ci][tap] -> [ci][tap][co] (removes a separate serialized launch).
// ---------------------------------------------------------------------------
__global__ __launch_bounds__(256) void softmax_causal_kernel(
        const float* __restrict__ scores, const float* __restrict__ weight) {
    if (blockIdx.x == gridDim.x - 1) {      // weight-transform block
        for (int t = threadIdx.x; t < CC * 25 * 16; t += blockDim.x) {
            int co  = t & 15;
            int tap = (t >> 4) % 25;
            int ci  = t / (16 * 25);
            g_wt[t] = weight[(co * CC + ci) * 25 + tap];
        }
        return;
    }

    const int row  = blockIdx.x * 8 + (threadIdx.x >> 5);   // (b*CC + c)*LLEN + i
    const int lane = threadIdx.x & 31;
    const int i    = row & (LLEN - 1);
    const float* src = scores + (size_t)row * LLEN;
    float* dst = g_probs + (size_t)row * LLEN;

    float4 v[8];
    float mx = -INFINITY;
#pragma unroll
    for (int k = 0; k < 8; k++) {
        const int j4 = (k * 32 + lane) * 4;
        float4 t = make_float4(-INFINITY, -INFINITY, -INFINITY, -INFINITY);
        if (j4 <= i) {
            t = *(const float4*)(src + j4);
            if (j4 + 1 > i) t.y = -INFINITY;
            if (j4 + 2 > i) t.z = -INFINITY;
            if (j4 + 3 > i) t.w = -INFINITY;
        }
        v[k] = t;
        mx = fmaxf(mx, fmaxf(fmaxf(t.x, t.y), fmaxf(t.z, t.w)));
    }
#pragma unroll
    for (int o = 16; o; o >>= 1) mx = fmaxf(mx, __shfl_xor_sync(0xffffffffu, mx, o));

    float s = 0.f;
#pragma unroll
    for (int k = 0; k < 8; k++) {
        float4 t = v[k];
        t.x = (t.x == -INFINITY) ? 0.f : __expf(t.x - mx);
        t.y = (t.y == -INFINITY) ? 0.f : __expf(t.y - mx);
        t.z = (t.z == -INFINITY) ? 0.f : __expf(t.z - mx);
        t.w = (t.w == -INFINITY) ? 0.f : __expf(t.w - mx);
        v[k] = t;
        s += (t.x + t.y) + (t.z + t.w);
    }
#pragma unroll
    for (int o = 16; o; o >>= 1) s += __shfl_xor_sync(0xffffffffu, s, o);
    const float inv = 1.0f / s;

#pragma unroll
    for (int k = 0; k < 8; k++) {
        const int j4 = (k * 32 + lane) * 4;
        if (j4 + 3 <= i) {
            float4 t = v[k];
            *(float4*)(dst + j4) = make_float4(t.x * inv, t.y * inv, t.z * inv, t.w * inv);
        } else if (j4 <= i) {
            float e[4] = {v[k].x, v[k].y, v[k].z, v[k].w};
#pragma unroll
            for (int q = 0; q < 4; q++)
                if (j4 + q <= i) dst[j4 + q] = e[q] * inv;
        }
    }
}

// ---------------------------------------------------------------------------
// cp.async staging of one chunk: CI_CHUNK input halo planes + that chunk's
// weights. Input src-size encodes range AND causality (hardware zero-fill):
// sz = clamp(gi-gj+1,0,2)*4. gj always even -> pairs never split rows.
// ---------------------------------------------------------------------------
__device__ __forceinline__ void issue_chunk_loads(
        const float* __restrict__ probs_b,   // g_probs + batch plane base
        int i0, int jt0, int cc, float* sbuf, float* wbuf, int tid)
{
    const unsigned int sbase = (unsigned int)__cvta_generic_to_shared(sbuf);
#pragma unroll
    for (int it = 0; it < (NPAIRS + 255) / 256; it++) {
        int e = tid + it * 256;
        if (e < NPAIRS) {
            int ci  = e / (SROWS * 34);
            int rem = e - ci * (SROWS * 34);
            int lr  = rem / 34;
            int m   = rem - lr * 34;
            int gi  = i0 - 2 + lr;
            int gj  = jt0 - 2 + 2 * m;
            bool okr = ((unsigned)gi < LLEN) && ((unsigned)gj < LLEN);
            int vis = gi - gj + 1;                       // causal elems in pair
            vis = vis < 0 ? 0 : (vis > 2 ? 2 : vis);
            int sz = okr ? vis * 4 : 0;
            const float* src = okr
                ? probs_b + ((size_t)(cc + ci) * LLEN + gi) * LLEN + gj
                : probs_b;                               // valid addr, size 0
            unsigned int dst = sbase + (unsigned int)(((ci * SROWS + lr) * SROW + 2 * m) * 4);
            asm volatile("cp.async.ca.shared.global [%0], [%1], 8, %2;"
                         :: "r"(dst), "l"(src), "r"(sz));
        }
    }
    // Weights for this chunk: contiguous [2ci][25tap][16co] block, 8B pairs.
    // WPAIRS(400) > blockDim(256) -> loop.
    const unsigned int wbase = (unsigned int)__cvta_generic_to_shared(wbuf);
#pragma unroll
    for (int it = 0; it < (WPAIRS + 255) / 256; it++) {
        int e = tid + it * 256;
        if (e < WPAIRS) {
            const float* wsrc = g_wt + cc * (25 * 16) + 2 * e;
            unsigned int wdst = wbase + (unsigned int)(8 * e);
            asm volatile("cp.async.ca.shared.global [%0], [%1], 8, 8;"
                         :: "r"(wdst), "l"(wsrc));
        }
    }
}

// ---------------------------------------------------------------------------
// Pass 2: 5x5 dense-channel conv + bias + causal zero-mask.
// FFMA2 compute (4 co-pairs x 8 pixels per thread), 3-buffer cp.async ring,
// ONE barrier per chunk, weights streamed per-chunk through the same ring.
// ki loop fully unrolled so ptxas can pipeline next-ki LDS under FFMA2s.
// ---------------------------------------------------------------------------
__global__ __launch_bounds__(256, 2) void conv_causal_kernel(
        const float* __restrict__ bias,     // [16]
        float* __restrict__ out)            // [b][co][i][j]
{
    const int cjt = blockIdx.x;             // 0..15  column tile
    const int rit = blockIdx.y;             // 0..63  row tile
    const int b   = blockIdx.z;             // 0..3
    const int i0  = rit * TH;
    const int jt0 = cjt * TW;

    const int tid = threadIdx.x;
    const int cg  = tid >> 7;               // 0/1 -> co 0-7 / 8-15 (warp-uniform)
    const int pg  = tid & 127;
    const int r   = pg >> 3;                // 0..15 tile row
    const int j0  = (pg & 7) * 8;           // 0,8,..,56 tile col group
    const int co_base = cg * 8;

    unsigned long long acc[4][8];
#pragma unroll
    for (int c = 0; c < 4; c++)
#pragma unroll
        for (int p = 0; p < 8; p++) acc[c][p] = 0ull;

    const bool tile_causal = (jt0 <= i0 + TH - 1);

    __shared__ __align__(16) float s_in[NBUF * CHUNK_ELEMS];   // 3 x 11.52 KB
    __shared__ __align__(16) float s_w[NBUF * WCHUNK];         // 3 x 3.2 KB

    if (tile_causal) {
        const float* probs_b = g_probs + (size_t)b * CC * LLEN * LLEN;

        // Prologue: stage chunk 0 (inputs + weights).
        issue_chunk_loads(probs_b, i0, jt0, 0, s_in, s_w, tid);
        asm volatile("cp.async.commit_group;" ::: "memory");

#pragma unroll 1
        for (int c = 0; c < NCHUNK; c++) {
            // Stage chunk c+1 into ring slot (c+1)%3. That slot was last read
            // during compute(c-2); every warp has passed sync(c-1), so it is
            // drained. Unconditional commit keeps wait_group counts exact.
            if (c + 1 < NCHUNK)
                issue_chunk_loads(probs_b, i0, jt0, (c + 1) * CI_CHUNK,
                                  s_in + ((c + 1) % NBUF) * CHUNK_ELEMS,
                                  s_w  + ((c + 1) % NBUF) * WCHUNK, tid);
            asm volatile("cp.async.commit_group;" ::: "memory");
            asm volatile("cp.async.wait_group 1;" ::: "memory");
            __syncthreads();   // single barrier per chunk: chunk c visible

            const float* cur = s_in + (c % NBUF) * CHUNK_ELEMS;
            const float* pin_base = cur + r * SROW + j0;
            const float* pw_base  = s_w + (c % NBUF) * WCHUNK + co_base;
#pragma unroll 1
            for (int ci = 0; ci < CI_CHUNK; ci++) {
                const float* wci = pw_base + ci * 400;
                const float* ici = pin_base + ci * (SROWS * SROW);
#pragma unroll
                for (int ki = 0; ki < 5; ki++) {          // FULL unroll: lets
                    const float* rp = ici + ki * SROW;    // ptxas pipeline LDS
                    float4 xa = *(const float4*)(rp);
                    float4 xb = *(const float4*)(rp + 4);
                    float4 xc = *(const float4*)(rp + 8);
                    unsigned long long pv[12];
                    pv[0]  = pack_dup(xa.x);  pv[1]  = pack_dup(xa.y);
                    pv[2]  = pack_dup(xa.z);  pv[3]  = pack_dup(xa.w);
                    pv[4]  = pack_dup(xb.x);  pv[5]  = pack_dup(xb.y);
                    pv[6]  = pack_dup(xb.z);  pv[7]  = pack_dup(xb.w);
                    pv[8]  = pack_dup(xc.x);  pv[9]  = pack_dup(xc.y);
                    pv[10] = pack_dup(xc.z);  pv[11] = pack_dup(xc.w);

                    const float* wk = wci + ki * 80;      // ki*5 taps * 16 co
#pragma unroll
                    for (int kj = 0; kj < 5; kj++) {
                        const ulonglong2 wA = *(const ulonglong2*)(wk + kj * 16);
                        const ulonglong2 wB = *(const ulonglong2*)(wk + kj * 16 + 4);
#pragma unroll
                        for (int p = 0; p < 8; p++) {
                            const unsigned long long xv = pv[p + kj];
                            ffma2(acc[0][p], wA.x, xv);
                            ffma2(acc[1][p], wA.y, xv);
                            ffma2(acc[2][p], wB.x, xv);
                            ffma2(acc[3][p], wB.y, xv);
                        }
                    }
                }
            }
        }
    }

    // Store: bias + causal mask. Non-causal tiles fall through with acc==0.
    const int ig = i0 + r;
    const int jg = jt0 + j0;
#pragma unroll
    for (int c2 = 0; c2 < 4; c2++) {
        const int coA = co_base + 2 * c2;
        const float bA = bias[coA];
        const float bB = bias[coA + 1];
        float oA[8], oB[8];
#pragma unroll
        for (int p = 0; p < 8; p++) {
            float lo, hi;
            unpack2(acc[c2][p], lo, hi);
            const bool ok = (jg + p <= ig);
            oA[p] = ok ? (lo + bA) : 0.f;
            oB[p] = ok ? (hi + bB) : 0.f;
        }
        float* opA = out + ((size_t)((b * CC + coA) * LLEN) + ig) * LLEN + jg;
        float* opB = opA + (size_t)LLEN * LLEN;
        *(float4*)opA       = make_float4(oA[0], oA[1], oA[2], oA[3]);
        *(float4*)(opA + 4) = make_float4(oA[4], oA[5], oA[6], oA[7]);
        *(float4*)opB       = make_float4(oB[0], oB[1], oB[2], oB[3]);
        *(float4*)(opB + 4) = make_float4(oB[4], oB[5], oB[6], oB[7]);
    }
}

// ---------------------------------------------------------------------------
// Launch
// ---------------------------------------------------------------------------
extern "C" void kernel_launch(void* const* d_in, const int* in_sizes, int n_in,
                              void* d_out, int out_size) {
    const float* scores = (const float*)d_in[0];  // [4,16,1024,1024]
    const float* weight = (const float*)d_in[1];  // [16,16,5,5]
    const float* bias   = (const float*)d_in[2];  // [16]
    float* out = (float*)d_out;

    // +1 block performs the weight transpose inside the softmax launch.
    softmax_causal_kernel<<<BB * CC * LLEN / 8 + 1, 256>>>(scores, weight);

    dim3 grid(LLEN / TW, LLEN / TH, BB);
    conv_causal_kernel<<<grid, 256>>>(bias, out);
}